// round 8
// baseline (speedup 1.0000x reference)
#include <cuda_runtime.h>

#define BATCH   16
#define NPTS    4096
#define NB      128
#define GROUPS  (NPTS / 32)          // 128 query groups of 32 per (dir,b)
#define NITEMS  (2 * BATCH * GROUPS) // 4096 work items
#define THREADS 256
#define GRIDP   444                  // persistent blocks (~3/SM)
#define XMIN_F  (-6.0f)
#define XMAX_F  (6.0f)
#define WBUCK   ((XMAX_F - XMIN_F) / (float)NB)
#define BSCALE  ((float)NB / (XMAX_F - XMIN_F))

__device__ double       g_acc[2];
__device__ float4       g_pts[2 * BATCH * NPTS];     // binned (x,y,z,||p||^2)
__device__ int          g_off[2 * BATCH * (NB + 1)]; // bucket prefix offsets
__device__ unsigned int g_ctr;                       // work-steal counter

// One block per (batch, set): histogram -> parallel prefix -> scatter.
__global__ __launch_bounds__(1024) void bin_kernel(
    const float* __restrict__ xyz1, const float* __restrict__ xyz2)
{
    const int b = blockIdx.x, set = blockIdx.y;
    if (b == 0 && set == 0 && threadIdx.x == 0) {
        g_acc[0] = 0.0; g_acc[1] = 0.0; g_ctr = 0u;
    }

    const float* __restrict__ src = ((set == 0) ? xyz1 : xyz2) + (size_t)b * NPTS * 3;
    __shared__ int cnt[NB];
    __shared__ int cur[NB + 1];
    __shared__ int wsum[NB / 32];
    const int tid = threadIdx.x;

    for (int k = tid; k < NB; k += 1024) cnt[k] = 0;
    __syncthreads();
    for (int i = tid; i < NPTS; i += 1024) {
        float x = src[3 * i];
        int bk = min(max((int)((x - XMIN_F) * BSCALE), 0), NB - 1);
        atomicAdd(&cnt[bk], 1);
    }
    __syncthreads();
    // Exclusive prefix over NB=128 buckets (4 warps shfl-scan).
    int v = 0, s = 0;
    if (tid < NB) {
        v = cnt[tid]; s = v;
#pragma unroll
        for (int o = 1; o < 32; o <<= 1) {
            int n = __shfl_up_sync(0xffffffffu, s, o);
            if ((tid & 31) >= o) s += n;
        }
        if ((tid & 31) == 31) wsum[tid >> 5] = s;
    }
    __syncthreads();
    if (tid < NB) {
        int add = 0;
#pragma unroll
        for (int k = 0; k < NB / 32; k++) if (k < (tid >> 5)) add += wsum[k];
        cur[tid] = s - v + add;
        if (tid == NB - 1) cur[NB] = s + add;
    }
    __syncthreads();
    int* off = g_off + (set * BATCH + b) * (NB + 1);
    for (int k = tid; k <= NB; k += 1024) off[k] = cur[k];
    float4* dst = g_pts + (set * BATCH + b) * NPTS;
    for (int i = tid; i < NPTS; i += 1024) {
        float x = src[3 * i], y = src[3 * i + 1], z = src[3 * i + 2];
        int bk = min(max((int)((x - XMIN_F) * BSCALE), 0), NB - 1);
        int pos = atomicAdd(&cur[bk], 1);
        dst[pos] = make_float4(x, y, z, x * x + y * y + z * z);
    }
}

// Scan one candidate bucket (uniform-address broadcast loads, L1-resident).
#define SCAN_BUCKET(J)                                                        \
    {                                                                         \
        int s_ = off[J], e_ = off[(J) + 1];                                   \
        _Pragma("unroll 4")                                                   \
        for (int i_ = s_; i_ < e_; i_++) {                                    \
            float4 cv = __ldg(&cp[i_]);                                       \
            float t_ = fmaf(qx, cv.x,                                         \
                       fmaf(qy, cv.y,                                         \
                       fmaf(qz, cv.z, cv.w)));                                \
            mn = fminf(mn, t_);                                               \
        }                                                                     \
    }

__global__ __launch_bounds__(THREADS) void chamfer_kernel()
{
    const int tid  = threadIdx.x;
    const int lane = tid & 31;
    const int warp = tid >> 5;
    __shared__ float red0[THREADS / 32];
    __shared__ float red1[THREADS / 32];

    float acc0 = 0.0f, acc1 = 0.0f;

    for (;;) {
        // Warp steals one item.
        unsigned int idx;
        if (lane == 0) idx = atomicAdd(&g_ctr, 1u);
        idx = __shfl_sync(0xffffffffu, idx, 0);
        if (idx >= NITEMS) break;

        // Decode: center groups first (LPT), (dir,b) fastest-varying.
        int pair   = idx & (2 * BATCH - 1);          // 0..31
        int g_rank = idx >> 5;                       // 0..127, 0 = most central
        int grp    = (g_rank & 1) ? (GROUPS / 2 + (g_rank >> 1))
                                  : (GROUPS / 2 - 1 - (g_rank >> 1));
        int dir = pair >> 4;
        int b   = pair & (BATCH - 1);

        const float4* __restrict__ qp  = g_pts + (dir * BATCH + b) * NPTS;
        const float4* __restrict__ cp  = g_pts + ((1 - dir) * BATCH + b) * NPTS;
        const int*    __restrict__ off = g_off + ((1 - dir) * BATCH + b) * (NB + 1);

        float4 qv = qp[grp * 32 + lane];
        float rx = qv.x;
        float qx = -2.0f * qv.x, qy = -2.0f * qv.y, qz = -2.0f * qv.z;
        float qs = qv.w;
        float mn = 3.4e38f;

        float xm = __shfl_sync(0xffffffffu, rx, 16);
        int jc = min(max((int)((xm - XMIN_F) * BSCALE), 0), NB - 1);

        SCAN_BUCKET(jc);

        bool ldone = false, rdone = false;
        for (int r = 1; r < NB; r++) {
            if (ldone && rdone) break;
            if (!ldone) {
                int j = jc - r;
                if (j < 0) ldone = true;
                else {
                    float el = XMIN_F + j * WBUCK;
                    float er = el + WBUCK;
                    // bucket 0 holds clamped outliers: left bound = -inf
                    float g = fmaxf(0.0f, fmaxf((j > 0) ? (el - rx) : 0.0f,
                                                rx - er));
                    if (__all_sync(0xffffffffu, g * g >= mn + qs)) ldone = true;
                    else SCAN_BUCKET(j);
                }
            }
            if (!rdone) {
                int j = jc + r;
                if (j >= NB) rdone = true;
                else {
                    float el = XMIN_F + j * WBUCK;
                    float er = el + WBUCK;
                    // bucket NB-1 holds clamped outliers: right bound = +inf
                    float g = fmaxf(0.0f, fmaxf(el - rx,
                                                (j < NB - 1) ? (rx - er) : 0.0f));
                    if (__all_sync(0xffffffffu, g * g >= mn + qs)) rdone = true;
                    else SCAN_BUCKET(j);
                }
            }
        }

        // True min distance for this lane's query.
        float d = mn + qs;
        if (dir == 0) acc0 += d; else acc1 += d;
    }

    // Block reduction, 2 atomics per block.
#pragma unroll
    for (int o = 16; o > 0; o >>= 1) {
        acc0 += __shfl_down_sync(0xffffffffu, acc0, o);
        acc1 += __shfl_down_sync(0xffffffffu, acc1, o);
    }
    if (lane == 0) { red0[warp] = acc0; red1[warp] = acc1; }
    __syncthreads();
    if (tid == 0) {
        float s0 = 0.0f, s1 = 0.0f;
#pragma unroll
        for (int w = 0; w < THREADS / 32; w++) { s0 += red0[w]; s1 += red1[w]; }
        if (s0 != 0.0f) atomicAdd(&g_acc[0], (double)s0);
        if (s1 != 0.0f) atomicAdd(&g_acc[1], (double)s1);
    }
}

__global__ void finalize_kernel(float* out) {
    if (threadIdx.x < 2)
        out[threadIdx.x] = (float)(g_acc[threadIdx.x] / (double)(BATCH * NPTS));
}

extern "C" void kernel_launch(void* const* d_in, const int* in_sizes, int n_in,
                              void* d_out, int out_size)
{
    const float* xyz1 = (const float*)d_in[0];
    const float* xyz2 = (const float*)d_in[1];
    float* out = (float*)d_out;

    bin_kernel<<<dim3(BATCH, 2), 1024>>>(xyz1, xyz2);
    chamfer_kernel<<<GRIDP, THREADS>>>();
    finalize_kernel<<<1, 32>>>(out);
}

// round 9
// speedup vs baseline: 2.5583x; 2.5583x over previous
#include <cuda_runtime.h>

#define BATCH   16
#define NPTS    4096
#define NB      128
#define THREADS 256
#define PPT     2
#define QPB     (THREADS * PPT)      // 512 queries per block
#define GRIDX   (NPTS / QPB)         // 8 -> grid (8,16,2) = 256 blocks
#define TILECAP 1024                 // smem candidate tile (16KB)
#define LSTEP   2                    // buckets per extension per side
#define XMIN_F  (-6.0f)
#define XMAX_F  (6.0f)
#define WBUCK   ((XMAX_F - XMIN_F) / (float)NB)
#define BSCALE  ((float)NB / (XMAX_F - XMIN_F))

__device__ double g_acc[2];
__device__ float4 g_pts[2 * BATCH * NPTS];        // binned (x,y,z,||p||^2)
__device__ int    g_off[2 * BATCH * (NB + 1)];    // bucket prefix offsets

// One block per (batch, set): histogram -> parallel prefix -> scatter.
__global__ __launch_bounds__(1024) void bin_kernel(
    const float* __restrict__ xyz1, const float* __restrict__ xyz2)
{
    const int b = blockIdx.x, set = blockIdx.y;
    if (b == 0 && set == 0 && threadIdx.x < 2) g_acc[threadIdx.x] = 0.0;

    const float* __restrict__ src = ((set == 0) ? xyz1 : xyz2) + (size_t)b * NPTS * 3;
    __shared__ int cnt[NB];
    __shared__ int cur[NB + 1];
    __shared__ int wsum[NB / 32];
    const int tid = threadIdx.x;

    for (int k = tid; k < NB; k += 1024) cnt[k] = 0;
    __syncthreads();
    for (int i = tid; i < NPTS; i += 1024) {
        float x = src[3 * i];
        int bk = min(max((int)((x - XMIN_F) * BSCALE), 0), NB - 1);
        atomicAdd(&cnt[bk], 1);
    }
    __syncthreads();
    int v = 0, s = 0;
    if (tid < NB) {
        v = cnt[tid]; s = v;
#pragma unroll
        for (int o = 1; o < 32; o <<= 1) {
            int n = __shfl_up_sync(0xffffffffu, s, o);
            if ((tid & 31) >= o) s += n;
        }
        if ((tid & 31) == 31) wsum[tid >> 5] = s;
    }
    __syncthreads();
    if (tid < NB) {
        int add = 0;
#pragma unroll
        for (int k = 0; k < NB / 32; k++) if (k < (tid >> 5)) add += wsum[k];
        cur[tid] = s - v + add;
        if (tid == NB - 1) cur[NB] = s + add;
    }
    __syncthreads();
    int* off = g_off + (set * BATCH + b) * (NB + 1);
    for (int k = tid; k <= NB; k += 1024) off[k] = cur[k];
    float4* dst = g_pts + (set * BATCH + b) * NPTS;
    for (int i = tid; i < NPTS; i += 1024) {
        float x = src[3 * i], y = src[3 * i + 1], z = src[3 * i + 2];
        int bk = min(max((int)((x - XMIN_F) * BSCALE), 0), NB - 1);
        int pos = atomicAdd(&cur[bk], 1);
        dst[pos] = make_float4(x, y, z, x * x + y * y + z * z);
    }
}

__global__ __launch_bounds__(THREADS) void chamfer_kernel()
{
    const int dir = blockIdx.z;
    const int b   = blockIdx.y;
    const int tid = threadIdx.x;

    __shared__ float4 tile[TILECAP];
    __shared__ int    soff[NB + 1];
    __shared__ int    sj[2];
    __shared__ float  red[THREADS / 32];

    const float4* __restrict__ qp = g_pts + (dir * BATCH + b) * NPTS;
    const float4* __restrict__ cp = g_pts + ((1 - dir) * BATCH + b) * NPTS;
    const int*    __restrict__ go = g_off + ((1 - dir) * BATCH + b) * (NB + 1);

    for (int k = tid; k <= NB; k += THREADS) soff[k] = go[k];

    // Load queries (sorted by bucket; chunk is a contiguous bucket-span).
    const int q0 = blockIdx.x * QPB;
    float rx[PPT], qx[PPT], qy[PPT], qz[PPT], qs[PPT], mn[PPT];
#pragma unroll
    for (int p = 0; p < PPT; p++) {
        float4 v = qp[q0 + tid + p * THREADS];
        rx[p] = v.x;
        qx[p] = -2.0f * v.x; qy[p] = -2.0f * v.y; qz[p] = -2.0f * v.z;
        qs[p] = v.w;
        mn[p] = 3.4e38f;
    }
    // First/last query bucket -> initial window (bucket order is monotone).
    if (tid == 0) {
        float xlo = qp[q0].x;
        sj[0] = min(max((int)((xlo - XMIN_F) * BSCALE), 0), NB - 1);
    }
    if (tid == THREADS - 1) {
        float xhi = qp[q0 + QPB - 1].x;
        sj[1] = min(max((int)((xhi - XMIN_F) * BSCALE), 0), NB - 1);
    }
    __syncthreads();
    int jlo = sj[0], jhi = sj[1];

    // Dense smem scan over a contiguous candidate span [m0, m1).
#define SCAN_SPAN(M0, M1)                                                     \
    for (int base_ = (M0); base_ < (M1); base_ += TILECAP) {                  \
        int cnt_ = min(TILECAP, (M1) - base_);                                \
        __syncthreads();                                                      \
        for (int i_ = tid; i_ < cnt_; i_ += THREADS) tile[i_] = cp[base_ + i_];\
        __syncthreads();                                                      \
        _Pragma("unroll 4")                                                   \
        for (int i_ = 0; i_ < cnt_; i_++) {                                   \
            float4 cv = tile[i_];                                             \
            _Pragma("unroll")                                                 \
            for (int p_ = 0; p_ < PPT; p_++) {                                \
                float t_ = fmaf(qx[p_], cv.x,                                 \
                           fmaf(qy[p_], cv.y,                                 \
                           fmaf(qz[p_], cv.z, cv.w)));                        \
                mn[p_] = fminf(mn[p_], t_);                                   \
            }                                                                 \
        }                                                                     \
    }

    // Initial window: buckets spanning the queries.
    SCAN_SPAN(soff[jlo], soff[jhi + 1]);

    // Extend outward, block-synchronous conservative votes.
    for (;;) {
        float elw = XMIN_F + jlo * WBUCK;            // scanned-window edges
        float erw = XMIN_F + (jhi + 1) * WBUCK;
        int lp = 1, rp = 1;
#pragma unroll
        for (int p = 0; p < PPT; p++) {
            float d  = mn[p] + qs[p];                // true min dist^2 so far
            float gl = fmaxf(rx[p] - elw, 0.0f);
            float gr = fmaxf(erw - rx[p], 0.0f);
            lp = lp && (gl * gl >= d);
            rp = rp && (gr * gr >= d);
        }
        int ldone = (jlo == 0)      || __syncthreads_and(lp);
        int rdone = (jhi == NB - 1) || __syncthreads_and(rp);
        if (ldone && rdone) break;
        if (!ldone) {
            int nj = max(jlo - LSTEP, 0);
            SCAN_SPAN(soff[nj], soff[jlo]);
            jlo = nj;
        }
        if (!rdone) {
            int nj = min(jhi + LSTEP, NB - 1);
            SCAN_SPAN(soff[jhi + 1], soff[nj + 1]);
            jhi = nj;
        }
    }

    // Sum true min distances; block reduce; one atomic per block.
    float s = 0.0f;
#pragma unroll
    for (int p = 0; p < PPT; p++) s += mn[p] + qs[p];
#pragma unroll
    for (int o = 16; o > 0; o >>= 1) s += __shfl_down_sync(0xffffffffu, s, o);
    if ((tid & 31) == 0) red[tid >> 5] = s;
    __syncthreads();
    if (tid < THREADS / 32) {
        s = red[tid];
#pragma unroll
        for (int o = (THREADS / 64); o > 0; o >>= 1)
            s += __shfl_down_sync(0xffu, s, o);
        if (tid == 0) atomicAdd(&g_acc[dir], (double)s);
    }
}

__global__ void finalize_kernel(float* out) {
    if (threadIdx.x < 2)
        out[threadIdx.x] = (float)(g_acc[threadIdx.x] / (double)(BATCH * NPTS));
}

extern "C" void kernel_launch(void* const* d_in, const int* in_sizes, int n_in,
                              void* d_out, int out_size)
{
    const float* xyz1 = (const float*)d_in[0];
    const float* xyz2 = (const float*)d_in[1];
    float* out = (float*)d_out;

    bin_kernel<<<dim3(BATCH, 2), 1024>>>(xyz1, xyz2);
    chamfer_kernel<<<dim3(GRIDX, BATCH, 2), THREADS>>>();   // 256 blocks
    finalize_kernel<<<1, 32>>>(out);
}

// round 10
// speedup vs baseline: 3.3925x; 1.3261x over previous
#include <cuda_runtime.h>

#define BATCH   16
#define NPTS    4096
#define NB      128
#define THREADS 256
#define PPT     2
#define QPB     (THREADS * PPT)      // 512 queries per block
#define GRIDX   (NPTS / QPB)         // 8 -> phase1 grid (8,16,2)
#define TILECAP 1024                 // smem candidate tile (16KB)
#define MARGIN  4                    // phase-1 window margin (buckets)
#define CSPLIT  8                    // phase-2 candidate splits
#define CSEG    (NPTS / CSPLIT)      // 512
#define XMIN_F  (-6.0f)
#define XMAX_F  (6.0f)
#define WBUCK   ((XMAX_F - XMIN_F) / (float)NB)
#define BSCALE  ((float)NB / (XMAX_F - XMIN_F))

__device__ double       g_acc[2];
__device__ float4       g_pts[2 * BATCH * NPTS];     // binned (x,y,z,||p||^2)
__device__ int          g_off[2 * BATCH * (NB + 1)];
__device__ int          g_fcnt[2 * BATCH];           // flagged count per pair
__device__ int          g_fidx[2 * BATCH * NPTS];    // flagged query indices
__device__ unsigned int g_fmin[2 * BATCH * NPTS];    // flagged partial mins (enc)

__device__ __forceinline__ unsigned int enc_f(float f) {
    unsigned int u = __float_as_uint(f);
    return (u & 0x80000000u) ? ~u : (u | 0x80000000u);
}
__device__ __forceinline__ float dec_f(unsigned int k) {
    unsigned int u = (k & 0x80000000u) ? (k & 0x7FFFFFFFu) : ~k;
    return __uint_as_float(u);
}

// One block per (batch, set): histogram -> parallel prefix -> scatter.
__global__ __launch_bounds__(1024) void bin_kernel(
    const float* __restrict__ xyz1, const float* __restrict__ xyz2)
{
    const int b = blockIdx.x, set = blockIdx.y;
    if (b == 0 && set == 0) {
        if (threadIdx.x < 2)  g_acc[threadIdx.x] = 0.0;
        if (threadIdx.x < 2 * BATCH) g_fcnt[threadIdx.x] = 0;
    }

    const float* __restrict__ src = ((set == 0) ? xyz1 : xyz2) + (size_t)b * NPTS * 3;
    __shared__ int cnt[NB];
    __shared__ int cur[NB + 1];
    __shared__ int wsum[NB / 32];
    const int tid = threadIdx.x;

    for (int k = tid; k < NB; k += 1024) cnt[k] = 0;
    __syncthreads();
    for (int i = tid; i < NPTS; i += 1024) {
        float x = src[3 * i];
        int bk = min(max((int)((x - XMIN_F) * BSCALE), 0), NB - 1);
        atomicAdd(&cnt[bk], 1);
    }
    __syncthreads();
    int v = 0, s = 0;
    if (tid < NB) {
        v = cnt[tid]; s = v;
#pragma unroll
        for (int o = 1; o < 32; o <<= 1) {
            int n = __shfl_up_sync(0xffffffffu, s, o);
            if ((tid & 31) >= o) s += n;
        }
        if ((tid & 31) == 31) wsum[tid >> 5] = s;
    }
    __syncthreads();
    if (tid < NB) {
        int add = 0;
#pragma unroll
        for (int k = 0; k < NB / 32; k++) if (k < (tid >> 5)) add += wsum[k];
        cur[tid] = s - v + add;
        if (tid == NB - 1) cur[NB] = s + add;
    }
    __syncthreads();
    int* off = g_off + (set * BATCH + b) * (NB + 1);
    for (int k = tid; k <= NB; k += 1024) off[k] = cur[k];
    float4* dst = g_pts + (set * BATCH + b) * NPTS;
    for (int i = tid; i < NPTS; i += 1024) {
        float x = src[3 * i], y = src[3 * i + 1], z = src[3 * i + 2];
        int bk = min(max((int)((x - XMIN_F) * BSCALE), 0), NB - 1);
        int pos = atomicAdd(&cur[bk], 1);
        dst[pos] = make_float4(x, y, z, x * x + y * y + z * z);
    }
}

// Phase 1: fixed-window dense scan + per-query certification.
__global__ __launch_bounds__(THREADS) void phase1_kernel()
{
    const int dir  = blockIdx.z;
    const int b    = blockIdx.y;
    const int pair = dir * BATCH + b;
    const int tid  = threadIdx.x;
    const int lane = tid & 31;

    __shared__ float4 tile[TILECAP];
    __shared__ int    soff[NB + 1];
    __shared__ int    sj[2];
    __shared__ float  red[THREADS / 32];

    const float4* __restrict__ qp = g_pts + (dir * BATCH + b) * NPTS;
    const float4* __restrict__ cp = g_pts + ((1 - dir) * BATCH + b) * NPTS;
    const int*    __restrict__ go = g_off + ((1 - dir) * BATCH + b) * (NB + 1);

    for (int k = tid; k <= NB; k += THREADS) soff[k] = go[k];

    const int q0 = blockIdx.x * QPB;
    float rx[PPT], qx[PPT], qy[PPT], qz[PPT], qs[PPT], mn[PPT];
#pragma unroll
    for (int p = 0; p < PPT; p++) {
        float4 v = qp[q0 + tid + p * THREADS];
        rx[p] = v.x;
        qx[p] = -2.0f * v.x; qy[p] = -2.0f * v.y; qz[p] = -2.0f * v.z;
        qs[p] = v.w;
        mn[p] = 3.4e38f;
    }
    if (tid == 0) {
        sj[0] = min(max((int)((qp[q0].x - XMIN_F) * BSCALE), 0), NB - 1);
    }
    if (tid == THREADS - 1) {
        sj[1] = min(max((int)((qp[q0 + QPB - 1].x - XMIN_F) * BSCALE), 0), NB - 1);
    }
    __syncthreads();
    const int wl = max(sj[0] - MARGIN, 0);
    const int wh = min(sj[1] + MARGIN, NB - 1);
    const int m0 = soff[wl], m1 = soff[wh + 1];

    // Dense smem scan over the window.
    for (int base = m0; base < m1; base += TILECAP) {
        int cnt = min(TILECAP, m1 - base);
        __syncthreads();
        for (int i = tid; i < cnt; i += THREADS) tile[i] = cp[base + i];
        __syncthreads();
#pragma unroll 4
        for (int i = 0; i < cnt; i++) {
            float4 cv = tile[i];
#pragma unroll
            for (int p = 0; p < PPT; p++) {
                float t = fmaf(qx[p], cv.x,
                          fmaf(qy[p], cv.y,
                          fmaf(qz[p], cv.z, cv.w)));
                mn[p] = fminf(mn[p], t);
            }
        }
    }

    // Per-query certification; certified sum here, rest compacted.
    const float el = XMIN_F + wl * WBUCK;            // window edges
    const float er = XMIN_F + (wh + 1) * WBUCK;
    float s = 0.0f;
#pragma unroll
    for (int p = 0; p < PPT; p++) {
        float d = mn[p] + qs[p];                     // true min dist^2 in window
        bool cl = (wl == 0)      || ((rx[p] - el) * (rx[p] - el) >= d);
        bool cr = (wh == NB - 1) || ((er - rx[p]) * (er - rx[p]) >= d);
        bool cert = cl && cr;
        if (cert) s += d;
        unsigned bal = __ballot_sync(0xffffffffu, !cert);
        if (bal) {
            int leader = __ffs(bal) - 1;
            unsigned basepos = 0;
            if (lane == leader)
                basepos = (unsigned)atomicAdd(&g_fcnt[pair], __popc(bal));
            basepos = __shfl_sync(0xffffffffu, basepos, leader);
            if (!cert) {
                int rank = __popc(bal & ((1u << lane) - 1u));
                int slot = pair * NPTS + (int)basepos + rank;
                g_fidx[slot] = q0 + tid + p * THREADS;
                g_fmin[slot] = 0xFFFFFFFFu;
            }
        }
    }

#pragma unroll
    for (int o = 16; o > 0; o >>= 1) s += __shfl_down_sync(0xffffffffu, s, o);
    if (lane == 0) red[tid >> 5] = s;
    __syncthreads();
    if (tid < THREADS / 32) {
        s = red[tid];
#pragma unroll
        for (int o = (THREADS / 64); o > 0; o >>= 1)
            s += __shfl_down_sync(0xffu, s, o);
        if (tid == 0) atomicAdd(&g_acc[dir], (double)s);
    }
}

// Phase 2: brute-force only flagged queries, split over candidate segments.
__global__ __launch_bounds__(THREADS) void phase2_kernel()
{
    const int pair = blockIdx.y;                     // 0..31
    const int dir  = pair >> 4;
    const int b    = pair & (BATCH - 1);
    const int tid  = threadIdx.x;
    const int nf   = g_fcnt[pair];
    if (nf == 0) return;

    __shared__ float4 tile[CSEG];
    const float4* __restrict__ qp = g_pts + (dir * BATCH + b) * NPTS;
    const float4* __restrict__ cp = g_pts + ((1 - dir) * BATCH + b) * NPTS;

    const int seg = blockIdx.x * CSEG;
    for (int i = tid; i < CSEG; i += THREADS) tile[i] = cp[seg + i];
    __syncthreads();

    for (int f = tid; f < nf; f += THREADS) {
        int n = g_fidx[pair * NPTS + f];
        float4 qv = qp[n];
        float qx = -2.0f * qv.x, qy = -2.0f * qv.y, qz = -2.0f * qv.z;
        float m0 = 3.4e38f, m1 = 3.4e38f, m2 = 3.4e38f, m3 = 3.4e38f;
#pragma unroll 4
        for (int i = 0; i < CSEG; i += 4) {
            float4 c0 = tile[i],     c1 = tile[i + 1];
            float4 c2 = tile[i + 2], c3 = tile[i + 3];
            m0 = fminf(m0, fmaf(qx, c0.x, fmaf(qy, c0.y, fmaf(qz, c0.z, c0.w))));
            m1 = fminf(m1, fmaf(qx, c1.x, fmaf(qy, c1.y, fmaf(qz, c1.z, c1.w))));
            m2 = fminf(m2, fmaf(qx, c2.x, fmaf(qy, c2.y, fmaf(qz, c2.z, c2.w))));
            m3 = fminf(m3, fmaf(qx, c3.x, fmaf(qy, c3.y, fmaf(qz, c3.z, c3.w))));
        }
        float mn = fminf(fminf(m0, m1), fminf(m2, m3));
        atomicMin(&g_fmin[pair * NPTS + f], enc_f(mn));
    }
}

// Finalize: fold flagged mins + certified sums -> output means.
__global__ __launch_bounds__(512) void finalize_kernel(float* out)
{
    const int tid = threadIdx.x;
    float s0 = 0.0f, s1 = 0.0f;
    for (int pair = 0; pair < 2 * BATCH; pair++) {
        int nf = g_fcnt[pair];
        int dir = pair >> 4, b = pair & (BATCH - 1);
        const float4* qp = g_pts + (dir * BATCH + b) * NPTS;
        for (int f = tid; f < nf; f += 512) {
            float d = dec_f(g_fmin[pair * NPTS + f]) + qp[g_fidx[pair * NPTS + f]].w;
            if (dir == 0) s0 += d; else s1 += d;
        }
    }
    __shared__ float r0[16], r1[16];
#pragma unroll
    for (int o = 16; o > 0; o >>= 1) {
        s0 += __shfl_down_sync(0xffffffffu, s0, o);
        s1 += __shfl_down_sync(0xffffffffu, s1, o);
    }
    if ((tid & 31) == 0) { r0[tid >> 5] = s0; r1[tid >> 5] = s1; }
    __syncthreads();
    if (tid == 0) {
        float t0 = 0.0f, t1 = 0.0f;
#pragma unroll
        for (int w = 0; w < 16; w++) { t0 += r0[w]; t1 += r1[w]; }
        out[0] = (float)((g_acc[0] + (double)t0) / (double)(BATCH * NPTS));
        out[1] = (float)((g_acc[1] + (double)t1) / (double)(BATCH * NPTS));
    }
}

extern "C" void kernel_launch(void* const* d_in, const int* in_sizes, int n_in,
                              void* d_out, int out_size)
{
    const float* xyz1 = (const float*)d_in[0];
    const float* xyz2 = (const float*)d_in[1];
    float* out = (float*)d_out;

    bin_kernel<<<dim3(BATCH, 2), 1024>>>(xyz1, xyz2);
    phase1_kernel<<<dim3(GRIDX, BATCH, 2), THREADS>>>();   // 256 blocks
    phase2_kernel<<<dim3(CSPLIT, 2 * BATCH), THREADS>>>(); // 256 blocks
    finalize_kernel<<<1, 512>>>(out);
}

// round 11
// speedup vs baseline: 4.2608x; 1.2560x over previous
#include <cuda_runtime.h>

#define BATCH   16
#define NPTS    4096
#define NB      128
#define THREADS 256
#define PPT     2
#define QPB     (THREADS * PPT)      // 512 queries per block
#define GRIDX   (NPTS / QPB)         // 8 -> phase1 grid (8,16,2)
#define TILECAP 1024                 // smem candidate tile (16KB)
#define MARGIN  4                    // phase-1 window margin (buckets)
#define CSPLIT  8                    // phase-2 candidate splits
#define CSEG    (NPTS / CSPLIT)      // 512
#define XMIN_F  (-6.0f)
#define XMAX_F  (6.0f)
#define WBUCK   ((XMAX_F - XMIN_F) / (float)NB)
#define BSCALE  ((float)NB / (XMAX_F - XMIN_F))

__device__ double       g_acc[2];
__device__ float4       g_pts[2 * BATCH * NPTS];     // binned (x,y,z,||p||^2)
__device__ int          g_off[2 * BATCH * (NB + 1)];
__device__ int          g_fcnt[2 * BATCH];           // flagged count per pair
__device__ int          g_fidx[2 * BATCH * NPTS];    // flagged query indices
__device__ unsigned int g_fmin[2 * BATCH * NPTS];    // flagged partial mins (enc)

__device__ __forceinline__ unsigned int enc_f(float f) {
    unsigned int u = __float_as_uint(f);
    return (u & 0x80000000u) ? ~u : (u | 0x80000000u);
}
__device__ __forceinline__ float dec_f(unsigned int k) {
    unsigned int u = (k & 0x80000000u) ? (k & 0x7FFFFFFFu) : ~k;
    return __uint_as_float(u);
}

// One block per (batch, set): histogram -> parallel prefix -> scatter.
__global__ __launch_bounds__(1024) void bin_kernel(
    const float* __restrict__ xyz1, const float* __restrict__ xyz2)
{
    const int b = blockIdx.x, set = blockIdx.y;
    if (b == 0 && set == 0) {
        if (threadIdx.x < 2)  g_acc[threadIdx.x] = 0.0;
        if (threadIdx.x < 2 * BATCH) g_fcnt[threadIdx.x] = 0;
    }

    const float* __restrict__ src = ((set == 0) ? xyz1 : xyz2) + (size_t)b * NPTS * 3;
    __shared__ int cnt[NB];
    __shared__ int cur[NB + 1];
    __shared__ int wsum[NB / 32];
    const int tid = threadIdx.x;

    for (int k = tid; k < NB; k += 1024) cnt[k] = 0;
    __syncthreads();
    for (int i = tid; i < NPTS; i += 1024) {
        float x = src[3 * i];
        int bk = min(max((int)((x - XMIN_F) * BSCALE), 0), NB - 1);
        atomicAdd(&cnt[bk], 1);
    }
    __syncthreads();
    int v = 0, s = 0;
    if (tid < NB) {
        v = cnt[tid]; s = v;
#pragma unroll
        for (int o = 1; o < 32; o <<= 1) {
            int n = __shfl_up_sync(0xffffffffu, s, o);
            if ((tid & 31) >= o) s += n;
        }
        if ((tid & 31) == 31) wsum[tid >> 5] = s;
    }
    __syncthreads();
    if (tid < NB) {
        int add = 0;
#pragma unroll
        for (int k = 0; k < NB / 32; k++) if (k < (tid >> 5)) add += wsum[k];
        cur[tid] = s - v + add;
        if (tid == NB - 1) cur[NB] = s + add;
    }
    __syncthreads();
    int* off = g_off + (set * BATCH + b) * (NB + 1);
    for (int k = tid; k <= NB; k += 1024) off[k] = cur[k];
    float4* dst = g_pts + (set * BATCH + b) * NPTS;
    for (int i = tid; i < NPTS; i += 1024) {
        float x = src[3 * i], y = src[3 * i + 1], z = src[3 * i + 2];
        int bk = min(max((int)((x - XMIN_F) * BSCALE), 0), NB - 1);
        int pos = atomicAdd(&cur[bk], 1);
        dst[pos] = make_float4(x, y, z, x * x + y * y + z * z);
    }
}

// Phase 1: fixed-window dense scan + per-query certification.
__global__ __launch_bounds__(THREADS) void phase1_kernel()
{
    const int dir  = blockIdx.z;
    const int b    = blockIdx.y;
    const int pair = dir * BATCH + b;
    const int tid  = threadIdx.x;
    const int lane = tid & 31;

    __shared__ float4 tile[TILECAP];
    __shared__ int    soff[NB + 1];
    __shared__ int    sj[2];
    __shared__ float  red[THREADS / 32];

    const float4* __restrict__ qp = g_pts + (dir * BATCH + b) * NPTS;
    const float4* __restrict__ cp = g_pts + ((1 - dir) * BATCH + b) * NPTS;
    const int*    __restrict__ go = g_off + ((1 - dir) * BATCH + b) * (NB + 1);

    for (int k = tid; k <= NB; k += THREADS) soff[k] = go[k];

    const int q0 = blockIdx.x * QPB;
    float rx[PPT], qx[PPT], qy[PPT], qz[PPT], qs[PPT], mn[PPT];
#pragma unroll
    for (int p = 0; p < PPT; p++) {
        float4 v = qp[q0 + tid + p * THREADS];
        rx[p] = v.x;
        qx[p] = -2.0f * v.x; qy[p] = -2.0f * v.y; qz[p] = -2.0f * v.z;
        qs[p] = v.w;
        mn[p] = 3.4e38f;
    }
    if (tid == 0) {
        sj[0] = min(max((int)((qp[q0].x - XMIN_F) * BSCALE), 0), NB - 1);
    }
    if (tid == THREADS - 1) {
        sj[1] = min(max((int)((qp[q0 + QPB - 1].x - XMIN_F) * BSCALE), 0), NB - 1);
    }
    __syncthreads();
    const int wl = max(sj[0] - MARGIN, 0);
    const int wh = min(sj[1] + MARGIN, NB - 1);
    const int m0 = soff[wl], m1 = soff[wh + 1];

    // Dense smem scan over the window.
    for (int base = m0; base < m1; base += TILECAP) {
        int cnt = min(TILECAP, m1 - base);
        __syncthreads();
        for (int i = tid; i < cnt; i += THREADS) tile[i] = cp[base + i];
        __syncthreads();
#pragma unroll 4
        for (int i = 0; i < cnt; i++) {
            float4 cv = tile[i];
#pragma unroll
            for (int p = 0; p < PPT; p++) {
                float t = fmaf(qx[p], cv.x,
                          fmaf(qy[p], cv.y,
                          fmaf(qz[p], cv.z, cv.w)));
                mn[p] = fminf(mn[p], t);
            }
        }
    }

    // Per-query certification; certified sum here, rest compacted.
    const float el = XMIN_F + wl * WBUCK;            // window edges
    const float er = XMIN_F + (wh + 1) * WBUCK;
    float s = 0.0f;
#pragma unroll
    for (int p = 0; p < PPT; p++) {
        float d = mn[p] + qs[p];                     // true min dist^2 in window
        bool cl = (wl == 0)      || ((rx[p] - el) * (rx[p] - el) >= d);
        bool cr = (wh == NB - 1) || ((er - rx[p]) * (er - rx[p]) >= d);
        bool cert = cl && cr;
        if (cert) s += d;
        unsigned bal = __ballot_sync(0xffffffffu, !cert);
        if (bal) {
            int leader = __ffs(bal) - 1;
            unsigned basepos = 0;
            if (lane == leader)
                basepos = (unsigned)atomicAdd(&g_fcnt[pair], __popc(bal));
            basepos = __shfl_sync(0xffffffffu, basepos, leader);
            if (!cert) {
                int rank = __popc(bal & ((1u << lane) - 1u));
                int slot = pair * NPTS + (int)basepos + rank;
                g_fidx[slot] = q0 + tid + p * THREADS;
                g_fmin[slot] = 0xFFFFFFFFu;
            }
        }
    }

#pragma unroll
    for (int o = 16; o > 0; o >>= 1) s += __shfl_down_sync(0xffffffffu, s, o);
    if (lane == 0) red[tid >> 5] = s;
    __syncthreads();
    if (tid < THREADS / 32) {
        s = red[tid];
#pragma unroll
        for (int o = (THREADS / 64); o > 0; o >>= 1)
            s += __shfl_down_sync(0xffu, s, o);
        if (tid == 0) atomicAdd(&g_acc[dir], (double)s);
    }
}

// Phase 2: brute-force only flagged queries, split over candidate segments.
__global__ __launch_bounds__(THREADS) void phase2_kernel()
{
    const int pair = blockIdx.y;                     // 0..31
    const int dir  = pair >> 4;
    const int b    = pair & (BATCH - 1);
    const int tid  = threadIdx.x;
    const int nf   = g_fcnt[pair];
    if (nf == 0) return;

    __shared__ float4 tile[CSEG];
    const float4* __restrict__ qp = g_pts + (dir * BATCH + b) * NPTS;
    const float4* __restrict__ cp = g_pts + ((1 - dir) * BATCH + b) * NPTS;

    const int seg = blockIdx.x * CSEG;
    for (int i = tid; i < CSEG; i += THREADS) tile[i] = cp[seg + i];
    __syncthreads();

    for (int f = tid; f < nf; f += THREADS) {
        int n = g_fidx[pair * NPTS + f];
        float4 qv = qp[n];
        float qx = -2.0f * qv.x, qy = -2.0f * qv.y, qz = -2.0f * qv.z;
        float m0 = 3.4e38f, m1 = 3.4e38f, m2 = 3.4e38f, m3 = 3.4e38f;
#pragma unroll 4
        for (int i = 0; i < CSEG; i += 4) {
            float4 c0 = tile[i],     c1 = tile[i + 1];
            float4 c2 = tile[i + 2], c3 = tile[i + 3];
            m0 = fminf(m0, fmaf(qx, c0.x, fmaf(qy, c0.y, fmaf(qz, c0.z, c0.w))));
            m1 = fminf(m1, fmaf(qx, c1.x, fmaf(qy, c1.y, fmaf(qz, c1.z, c1.w))));
            m2 = fminf(m2, fmaf(qx, c2.x, fmaf(qy, c2.y, fmaf(qz, c2.z, c2.w))));
            m3 = fminf(m3, fmaf(qx, c3.x, fmaf(qy, c3.y, fmaf(qz, c3.z, c3.w))));
        }
        float mn = fminf(fminf(m0, m1), fminf(m2, m3));
        atomicMin(&g_fmin[pair * NPTS + f], enc_f(mn));
    }
}

// Fold flagged mins in parallel: one block per pair.
__global__ __launch_bounds__(THREADS) void fold_kernel()
{
    const int pair = blockIdx.x;                     // 0..31
    const int dir  = pair >> 4;
    const int b    = pair & (BATCH - 1);
    const int tid  = threadIdx.x;
    const int nf   = g_fcnt[pair];

    const float4* __restrict__ qp = g_pts + (dir * BATCH + b) * NPTS;
    float s = 0.0f;
    for (int f = tid; f < nf; f += THREADS)
        s += dec_f(g_fmin[pair * NPTS + f]) + qp[g_fidx[pair * NPTS + f]].w;

    __shared__ float red[THREADS / 32];
#pragma unroll
    for (int o = 16; o > 0; o >>= 1) s += __shfl_down_sync(0xffffffffu, s, o);
    if ((tid & 31) == 0) red[tid >> 5] = s;
    __syncthreads();
    if (tid < THREADS / 32) {
        s = red[tid];
#pragma unroll
        for (int o = (THREADS / 64); o > 0; o >>= 1)
            s += __shfl_down_sync(0xffu, s, o);
        if (tid == 0 && s != 0.0f) atomicAdd(&g_acc[dir], (double)s);
    }
}

__global__ void write_kernel(float* out) {
    if (threadIdx.x < 2)
        out[threadIdx.x] = (float)(g_acc[threadIdx.x] / (double)(BATCH * NPTS));
}

extern "C" void kernel_launch(void* const* d_in, const int* in_sizes, int n_in,
                              void* d_out, int out_size)
{
    const float* xyz1 = (const float*)d_in[0];
    const float* xyz2 = (const float*)d_in[1];
    float* out = (float*)d_out;

    bin_kernel<<<dim3(BATCH, 2), 1024>>>(xyz1, xyz2);
    phase1_kernel<<<dim3(GRIDX, BATCH, 2), THREADS>>>();   // 256 blocks
    phase2_kernel<<<dim3(CSPLIT, 2 * BATCH), THREADS>>>(); // 256 blocks
    fold_kernel<<<2 * BATCH, THREADS>>>();                 // 32 blocks
    write_kernel<<<1, 32>>>(out);
}